// round 10
// baseline (speedup 1.0000x reference)
#include <cuda_runtime.h>
#include <cuda_bf16.h>
#include <cstdint>
#include <math.h>

#define D      2048
#define BROWS  2048
#define SIZE   6144
#define BIJ    4096
#define TILE   128
#define KCB    128                    // k-elements (=bytes) per chunk, int8
#define NCHUNK (D / KCB)              // 16
#define NTILES 48
#define NBLOCKS (NTILES * (NTILES + 1) / 2)   // 1176 upper-triangle tiles

// Swizzled 128B rows: byte chunk cc (16B) of row r stored at (cc ^ (r&7))*16.
#define BUFSZ   (TILE * 128)          // 16384
// smem: A0,A1,A2,B0,B1,B2, rs(512), cs(512)
#define OFF_A(b) ((b) * BUFSZ)
#define OFF_B(b) ((3 + (b)) * BUFSZ)
#define OFF_RS  (6 * BUFSZ)
#define OFF_CS  (6 * BUFSZ + 512)
#define SMEM_TOTAL (6 * BUFSZ + 1024)

// Scratch (device globals: allocation-free per harness rules)
__device__ uint8_t g_z8[(size_t)SIZE * D];   // round(256 * normalized emb), int8
__device__ float g_denom[SIZE];
__device__ float g_num[SIZE];
__device__ int   g_ctr;                      // completed-tile counter (reset each launch)

__device__ __forceinline__ uint32_t smem_u32(const void* p) {
    uint32_t a;
    asm("{ .reg .u64 t; cvta.to.shared.u64 t, %1; cvt.u32.u64 %0, t; }" : "=r"(a) : "l"(p));
    return a;
}
__device__ __forceinline__ float fast_ex2(float x) {
    float y; asm("ex2.approx.ftz.f32 %0, %1;" : "=f"(y) : "f"(x)); return y;
}
__device__ __forceinline__ float fast_lg2(float x) {
    float y; asm("lg2.approx.f32 %0, %1;" : "=f"(y) : "f"(x)); return y;
}
__device__ __forceinline__ uint32_t to_s8(float x) {
    uint32_t r;
    asm("cvt.rni.sat.s8.f32 %0, %1;" : "=r"(r) : "f"(x));
    return r & 0xFFu;
}
__device__ __forceinline__ uint32_t pack4_s8(float a, float b, float c, float d) {
    return to_s8(a) | (to_s8(b) << 8) | (to_s8(c) << 16) | (to_s8(d) << 24);
}
__device__ __forceinline__ void cp16(uint32_t dst, const void* src) {
    asm volatile("cp.async.cg.shared.global [%0], [%1], 16;" :: "r"(dst), "l"(src));
}
#define CP_COMMIT()  asm volatile("cp.async.commit_group;" ::: "memory")
#define CP_WAIT1()   asm volatile("cp.async.wait_group 1;" ::: "memory")
#define CP_WAIT0()   asm volatile("cp.async.wait_group 0;" ::: "memory")

__device__ __forceinline__ void ldsm4(uint32_t* r, uint32_t addr) {
    asm volatile("ldmatrix.sync.aligned.m8n8.x4.shared.b16 {%0,%1,%2,%3}, [%4];"
                 : "=r"(r[0]), "=r"(r[1]), "=r"(r[2]), "=r"(r[3]) : "r"(addr));
}
__device__ __forceinline__ void mma_s8(int c[4], const uint32_t a[4], const uint32_t b[2]) {
    asm volatile(
        "mma.sync.aligned.m16n8k32.row.col.s32.s8.s8.s32 "
        "{%0,%1,%2,%3}, {%4,%5,%6,%7}, {%8,%9}, {%0,%1,%2,%3};"
        : "+r"(c[0]), "+r"(c[1]), "+r"(c[2]), "+r"(c[3])
        : "r"(a[0]), "r"(a[1]), "r"(a[2]), "r"(a[3]), "r"(b[0]), "r"(b[1]));
}

// ---------------------------------------------------------------------------
// Kernel 1: L2-normalize -> int8 (x256). One warp per row, TWO PASSES over
// the row (no register retention -> high occupancy). Grid 768 x 256.
// ---------------------------------------------------------------------------
__global__ __launch_bounds__(256, 8)
void k_normalize(const float* __restrict__ e0,
                 const float* __restrict__ e1,
                 const float* __restrict__ e2) {
    const int lane = threadIdx.x & 31;
    const int row  = blockIdx.x * 8 + (threadIdx.x >> 5);
    if (lane == 0) { g_denom[row] = 0.f; g_num[row] = 0.f; }
    if (blockIdx.x == 0 && threadIdx.x == 0) g_ctr = 0;

    const float* src;
    if (row < BROWS)            src = e0 + (size_t)row * D;
    else if (row < 2 * BROWS)   src = e1 + (size_t)(row - BROWS) * D;
    else                        src = e2 + (size_t)(row - 2 * BROWS) * D;
    const float4* s4 = (const float4*)src;

    // pass 1: sum of squares (streaming, nothing retained)
    float ss = 0.f;
    #pragma unroll
    for (int it = 0; it < 16; it++) {
        float4 x = s4[lane + 32 * it];
        ss += x.x * x.x + x.y * x.y + x.z * x.z + x.w * x.w;
    }
    #pragma unroll
    for (int o = 16; o; o >>= 1) ss += __shfl_xor_sync(0xffffffffu, ss, o);

    float inv = 256.0f / fmaxf(sqrtf(ss), 1e-12f);

    // pass 2: reload (L2-resident) and quantize
    uint32_t* d32 = (uint32_t*)(g_z8 + (size_t)row * D);
    #pragma unroll
    for (int it = 0; it < 16; it++) {
        float4 x = s4[lane + 32 * it];
        d32[lane + 32 * it] = pack4_s8(x.x * inv, x.y * inv, x.z * inv, x.w * inv);
    }
}

// ---------------------------------------------------------------------------
// Kernel 2: upper-triangle tiles, int8 mma, 3-stage cp.async pipeline,
// swizzled smem, one barrier per chunk. Last finishing block computes loss.
// 256 threads = 8 warps, 2(M) x 4(N).
// ---------------------------------------------------------------------------
__device__ __forceinline__ void stage_chunk(uint32_t sb, uint32_t aOff, uint32_t bOff,
                                            int rowBase, int colBase, int k0, int tid) {
    #pragma unroll
    for (int it = 0; it < 4; it++) {
        int id = tid + it * 256;          // 0..1023
        int r  = id >> 3;                 // 0..127
        int cc = id & 7;                  // 16B chunk within row
        uint32_t o = (uint32_t)(r * 128 + ((cc ^ (r & 7)) << 4));
        cp16(sb + aOff + o, g_z8 + (size_t)(rowBase + r) * D + k0 + cc * 16);
        cp16(sb + bOff + o, g_z8 + (size_t)(colBase + r) * D + k0 + cc * 16);
    }
}

__global__ __launch_bounds__(256, 2)
void k_sim(float* __restrict__ out) {
    extern __shared__ char smem[];
    const uint32_t sb = smem_u32(smem);
    float* rs = (float*)(smem + OFF_RS);
    float* cs = (float*)(smem + OFF_CS);

    // Triangular decode: t = i*(i+1)/2 + j with j <= i; rowTile=j, colTile=i
    int t = blockIdx.x;
    int i = (int)((sqrtf(8.0f * (float)t + 1.0f) - 1.0f) * 0.5f);
    while ((i + 1) * (i + 2) / 2 <= t) i++;
    while (i * (i + 1) / 2 > t) i--;
    int j = t - i * (i + 1) / 2;

    const int rowBase = j * TILE;
    const int colBase = i * TILE;
    const bool diagTile = (i == j);

    const int tid  = threadIdx.x;
    const int wid  = tid >> 5;
    const int lane = tid & 31;
    const int mBase = (wid >> 2) * 64;   // warpM in {0,1}
    const int nBase = (wid & 3) * 32;    // warpN in {0..3}
    const int gid = lane >> 2;
    const int tig = lane & 3;

    if (tid < 2 * TILE) ((float*)(smem + OFF_RS))[tid] = 0.f;

    // ldmatrix lane addressing (swizzled)
    const int aRow = mBase + (lane & 15);          // +ms*16 preserves &7
    const uint32_t aXor = (uint32_t)(aRow & 7);
    const uint32_t aHi  = (lane & 16) ? 1u : 0u;
    const int bRow = nBase + ((lane & 16) ? 8 : 0) + (lane & 7);   // +p*16 preserves &7
    const uint32_t bXor = (uint32_t)(bRow & 7);
    const uint32_t bHi  = (lane & 8) ? 1u : 0u;

    int acc[4][4][4] = {};               // [msub][nsub][frag], int32

    // prologue: prefetch chunks 0,1
    stage_chunk(sb, OFF_A(0), OFF_B(0), rowBase, colBase, 0, tid);
    CP_COMMIT();
    stage_chunk(sb, OFF_A(1), OFF_B(1), rowBase, colBase, KCB, tid);
    CP_COMMIT();

    int buf = 0;
    #pragma unroll 4
    for (int c = 0; c < NCHUNK; c++) {
        if (c == NCHUNK - 1) { CP_WAIT0(); } else { CP_WAIT1(); }
        __syncthreads();

        const uint32_t aB = sb + OFF_A(buf);
        const uint32_t bB = sb + OFF_B(buf);

        // 4 k-steps of 32 int8 (32 bytes = 2 swizzled chunks) each
        #pragma unroll
        for (int kk = 0; kk < KCB; kk += 32) {
            const uint32_t ch = (uint32_t)(kk >> 4);
            uint32_t a[4][4];
            uint32_t b[2][4];            // [n-pair][(ns even:0,1)(ns odd:2,3)]
            #pragma unroll
            for (int ms = 0; ms < 4; ms++)
                ldsm4(a[ms], aB + (uint32_t)(aRow + ms * 16) * 128
                                + (((ch + aHi) ^ aXor) << 4));
            #pragma unroll
            for (int p = 0; p < 2; p++)
                ldsm4(b[p], bB + (uint32_t)(bRow + p * 16) * 128
                               + (((ch + bHi) ^ bXor) << 4));

            #pragma unroll
            for (int ms = 0; ms < 4; ms++) {
                mma_s8(acc[ms][0], a[ms], &b[0][0]);
                mma_s8(acc[ms][1], a[ms], &b[0][2]);
                mma_s8(acc[ms][2], a[ms], &b[1][0]);
                mma_s8(acc[ms][3], a[ms], &b[1][2]);
            }
        }

        // stage chunk c+2 into buffer (c+2)%3 (its last reader finished at
        // iter c-1, proven by this iteration's barrier)
        if (c + 2 < NCHUNK) {
            int nb = buf + 2; if (nb >= 3) nb -= 3;
            stage_chunk(sb, OFF_A(nb), OFF_B(nb), rowBase, colBase, (c + 2) * KCB, tid);
            CP_COMMIT();
        }
        buf = (buf == 2) ? 0 : buf + 1;
    }

    // exp, diagonal exclusion, row + column sums
    // acc = 65536 * sim  ->  scale = 10*log2(e)/65536
    const float SCALE = 14.4269504088896340736f / 65536.0f;

    float colAcc[4][2] = {};

    #pragma unroll
    for (int ms = 0; ms < 4; ms++) {
        int r0 = mBase + ms * 16 + gid;
        float s0 = 0.f, s1 = 0.f;
        #pragma unroll
        for (int ns = 0; ns < 4; ns++) {
            int c0 = nBase + ns * 8 + tig * 2;
            float v0 = fast_ex2((float)acc[ms][ns][0] * SCALE);
            float v1 = fast_ex2((float)acc[ms][ns][1] * SCALE);
            float v2 = fast_ex2((float)acc[ms][ns][2] * SCALE);
            float v3 = fast_ex2((float)acc[ms][ns][3] * SCALE);
            if (diagTile) {
                if (r0 == c0)         v0 = 0.f;
                if (r0 == c0 + 1)     v1 = 0.f;
                if (r0 + 8 == c0)     v2 = 0.f;
                if (r0 + 8 == c0 + 1) v3 = 0.f;
            }
            s0 += v0 + v1;
            s1 += v2 + v3;
            colAcc[ns][0] += v0 + v2;
            colAcc[ns][1] += v1 + v3;
        }
        s0 += __shfl_xor_sync(0xffffffffu, s0, 1);
        s0 += __shfl_xor_sync(0xffffffffu, s0, 2);
        s1 += __shfl_xor_sync(0xffffffffu, s1, 1);
        s1 += __shfl_xor_sync(0xffffffffu, s1, 2);
        if (tig == 0) {
            atomicAdd(&rs[r0], s0);
            atomicAdd(&rs[r0 + 8], s1);
        }
    }

    if (!diagTile) {
        #pragma unroll
        for (int ns = 0; ns < 4; ns++) {
            float c0v = colAcc[ns][0];
            float c1v = colAcc[ns][1];
            #pragma unroll
            for (int o = 4; o <= 16; o <<= 1) {
                c0v += __shfl_xor_sync(0xffffffffu, c0v, o);
                c1v += __shfl_xor_sync(0xffffffffu, c1v, o);
            }
            if (gid == 0) {
                int c0 = nBase + ns * 8 + tig * 2;
                atomicAdd(&cs[c0], c0v);
                atomicAdd(&cs[c0 + 1], c1v);
            }
        }
    }
    __syncthreads();

    if (tid < TILE) {
        bool inNum = ((rowBase < BIJ) == (colBase < BIJ));
        float rv = rs[tid];
        atomicAdd(&g_denom[rowBase + tid], rv);
        if (inNum) atomicAdd(&g_num[rowBase + tid], rv);
        if (!diagTile) {
            float cv = cs[tid];
            atomicAdd(&g_denom[colBase + tid], cv);
            if (inNum) atomicAdd(&g_num[colBase + tid], cv);
        }
    }

    // ---- last-block loss reduction (replaces k_loss kernel) ----
    __threadfence();            // all threads: make this block's atomics visible
    __syncthreads();
    __shared__ int lastFlag;
    if (tid == 0) {
        int old = atomicAdd(&g_ctr, 1);
        lastFlag = (old == NBLOCKS - 1);
    }
    __syncthreads();
    if (!lastFlag) return;
    __threadfence();            // acquire: all blocks' g_denom/g_num visible

    const float LN2 = 0.6931471805599453f;
    float s = 0.f;
    for (int ii = tid; ii < SIZE; ii += 256) {
        float cntm1 = (ii < BIJ) ? (float)(BIJ - 1) : (float)(BROWS - 1);
        s += (fast_lg2(g_denom[ii]) - fast_lg2(g_num[ii]) + fast_lg2(cntm1)) * LN2;
    }
    #pragma unroll
    for (int o = 16; o; o >>= 1) s += __shfl_xor_sync(0xffffffffu, s, o);
    if ((tid & 31) == 0) rs[tid >> 5] = s;     // reuse smem rs
    __syncthreads();
    if (tid == 0) {
        float tsum = rs[0] + rs[1] + rs[2] + rs[3] + rs[4] + rs[5] + rs[6] + rs[7];
        out[0] = tsum / (float)SIZE;
    }
}

// ---------------------------------------------------------------------------
extern "C" void kernel_launch(void* const* d_in, const int* in_sizes, int n_in,
                              void* d_out, int out_size) {
    const float* emb_i = (const float*)d_in[0];
    const float* emb_j = (const float*)d_in[1];
    const float* emb_k = (const float*)d_in[2];
    float* out = (float*)d_out;

    cudaFuncSetAttribute(k_sim, cudaFuncAttributeMaxDynamicSharedMemorySize, SMEM_TOTAL);

    k_normalize<<<SIZE / 8, 256>>>(emb_i, emb_j, emb_k);
    k_sim<<<NBLOCKS, 256, SMEM_TOTAL>>>(out);
}

// round 11
// speedup vs baseline: 1.1578x; 1.1578x over previous
#include <cuda_runtime.h>
#include <cuda_bf16.h>
#include <cstdint>
#include <math.h>

#define D      2048
#define BROWS  2048
#define SIZE   6144
#define BIJ    4096
#define TILE   128
#define KCB    128                    // k-elements (=bytes) per chunk, int8
#define NCHUNK (D / KCB)              // 16
#define NTILES 48
#define NBLOCKS (NTILES * (NTILES + 1) / 2)   // 1176 upper-triangle tiles

// Swizzled 128B rows: byte chunk cc (16B) of row r stored at (cc ^ (r&7))*16.
#define BUFSZ   (TILE * 128)          // 16384
// smem: A0,A1,A2,B0,B1,B2, rs(512), cs(512)
#define OFF_A(b) ((b) * BUFSZ)
#define OFF_B(b) ((3 + (b)) * BUFSZ)
#define OFF_RS  (6 * BUFSZ)
#define OFF_CS  (6 * BUFSZ + 512)
#define SMEM_TOTAL (6 * BUFSZ + 1024)

// Scratch (device globals: allocation-free per harness rules)
__device__ uint8_t g_z8[(size_t)SIZE * D];   // round(256 * normalized emb), int8
__device__ float g_denom[SIZE];
__device__ float g_num[SIZE];

__device__ __forceinline__ uint32_t smem_u32(const void* p) {
    uint32_t a;
    asm("{ .reg .u64 t; cvta.to.shared.u64 t, %1; cvt.u32.u64 %0, t; }" : "=r"(a) : "l"(p));
    return a;
}
__device__ __forceinline__ float fast_ex2(float x) {
    float y; asm("ex2.approx.ftz.f32 %0, %1;" : "=f"(y) : "f"(x)); return y;
}
__device__ __forceinline__ float fast_lg2(float x) {
    float y; asm("lg2.approx.f32 %0, %1;" : "=f"(y) : "f"(x)); return y;
}
__device__ __forceinline__ uint32_t to_s8(float x) {
    uint32_t r;
    asm("cvt.rni.sat.s8.f32 %0, %1;" : "=r"(r) : "f"(x));
    return r & 0xFFu;
}
__device__ __forceinline__ uint32_t pack4_s8(float a, float b, float c, float d) {
    return to_s8(a) | (to_s8(b) << 8) | (to_s8(c) << 16) | (to_s8(d) << 24);
}
__device__ __forceinline__ void cp16(uint32_t dst, const void* src) {
    asm volatile("cp.async.cg.shared.global [%0], [%1], 16;" :: "r"(dst), "l"(src));
}
#define CP_COMMIT()  asm volatile("cp.async.commit_group;" ::: "memory")
#define CP_WAIT1()   asm volatile("cp.async.wait_group 1;" ::: "memory")
#define CP_WAIT0()   asm volatile("cp.async.wait_group 0;" ::: "memory")

__device__ __forceinline__ void ldsm4(uint32_t* r, uint32_t addr) {
    asm volatile("ldmatrix.sync.aligned.m8n8.x4.shared.b16 {%0,%1,%2,%3}, [%4];"
                 : "=r"(r[0]), "=r"(r[1]), "=r"(r[2]), "=r"(r[3]) : "r"(addr));
}
__device__ __forceinline__ void mma_s8(int c[4], const uint32_t a[4], const uint32_t b[2]) {
    asm volatile(
        "mma.sync.aligned.m16n8k32.row.col.s32.s8.s8.s32 "
        "{%0,%1,%2,%3}, {%4,%5,%6,%7}, {%8,%9}, {%0,%1,%2,%3};"
        : "+r"(c[0]), "+r"(c[1]), "+r"(c[2]), "+r"(c[3])
        : "r"(a[0]), "r"(a[1]), "r"(a[2]), "r"(a[3]), "r"(b[0]), "r"(b[1]));
}

// ---------------------------------------------------------------------------
// Kernel 1: L2-normalize -> int8 (x256). One warp per row, TWO PASSES over
// the row (no register retention -> high occupancy). Grid 768 x 256.
// ---------------------------------------------------------------------------
__global__ __launch_bounds__(256, 8)
void k_normalize(const float* __restrict__ e0,
                 const float* __restrict__ e1,
                 const float* __restrict__ e2) {
    const int lane = threadIdx.x & 31;
    const int row  = blockIdx.x * 8 + (threadIdx.x >> 5);
    if (lane == 0) { g_denom[row] = 0.f; g_num[row] = 0.f; }

    const float* src;
    if (row < BROWS)            src = e0 + (size_t)row * D;
    else if (row < 2 * BROWS)   src = e1 + (size_t)(row - BROWS) * D;
    else                        src = e2 + (size_t)(row - 2 * BROWS) * D;
    const float4* s4 = (const float4*)src;

    // pass 1: sum of squares (streaming, nothing retained)
    float ss = 0.f;
    #pragma unroll
    for (int it = 0; it < 16; it++) {
        float4 x = s4[lane + 32 * it];
        ss += x.x * x.x + x.y * x.y + x.z * x.z + x.w * x.w;
    }
    #pragma unroll
    for (int o = 16; o; o >>= 1) ss += __shfl_xor_sync(0xffffffffu, ss, o);

    float inv = 256.0f / fmaxf(sqrtf(ss), 1e-12f);

    // pass 2: reload (L2-resident) and quantize
    uint32_t* d32 = (uint32_t*)(g_z8 + (size_t)row * D);
    #pragma unroll
    for (int it = 0; it < 16; it++) {
        float4 x = s4[lane + 32 * it];
        d32[lane + 32 * it] = pack4_s8(x.x * inv, x.y * inv, x.z * inv, x.w * inv);
    }
}

// ---------------------------------------------------------------------------
// Kernel 2: upper-triangle tiles, int8 mma, 3-stage cp.async pipeline,
// swizzled smem, one barrier per chunk (R8 structure, proven fastest).
// 256 threads = 8 warps, 2(M) x 4(N).
// ---------------------------------------------------------------------------
__device__ __forceinline__ void stage_chunk(uint32_t sb, uint32_t aOff, uint32_t bOff,
                                            int rowBase, int colBase, int k0, int tid) {
    #pragma unroll
    for (int it = 0; it < 4; it++) {
        int id = tid + it * 256;          // 0..1023
        int r  = id >> 3;                 // 0..127
        int cc = id & 7;                  // 16B chunk within row
        uint32_t o = (uint32_t)(r * 128 + ((cc ^ (r & 7)) << 4));
        cp16(sb + aOff + o, g_z8 + (size_t)(rowBase + r) * D + k0 + cc * 16);
        cp16(sb + bOff + o, g_z8 + (size_t)(colBase + r) * D + k0 + cc * 16);
    }
}

__global__ __launch_bounds__(256, 2)
void k_sim() {
    extern __shared__ char smem[];
    const uint32_t sb = smem_u32(smem);
    float* rs = (float*)(smem + OFF_RS);
    float* cs = (float*)(smem + OFF_CS);

    // Triangular decode: t = i*(i+1)/2 + j with j <= i; rowTile=j, colTile=i
    int t = blockIdx.x;
    int i = (int)((sqrtf(8.0f * (float)t + 1.0f) - 1.0f) * 0.5f);
    while ((i + 1) * (i + 2) / 2 <= t) i++;
    while (i * (i + 1) / 2 > t) i--;
    int j = t - i * (i + 1) / 2;

    const int rowBase = j * TILE;
    const int colBase = i * TILE;
    const bool diagTile = (i == j);

    const int tid  = threadIdx.x;
    const int wid  = tid >> 5;
    const int lane = tid & 31;
    const int mBase = (wid >> 2) * 64;   // warpM in {0,1}
    const int nBase = (wid & 3) * 32;    // warpN in {0..3}
    const int gid = lane >> 2;
    const int tig = lane & 3;

    if (tid < 2 * TILE) ((float*)(smem + OFF_RS))[tid] = 0.f;

    // ldmatrix lane addressing (swizzled)
    const int aRow = mBase + (lane & 15);          // +ms*16 preserves &7
    const uint32_t aXor = (uint32_t)(aRow & 7);
    const uint32_t aHi  = (lane & 16) ? 1u : 0u;
    const int bRow = nBase + ((lane & 16) ? 8 : 0) + (lane & 7);   // +p*16 preserves &7
    const uint32_t bXor = (uint32_t)(bRow & 7);
    const uint32_t bHi  = (lane & 8) ? 1u : 0u;

    int acc[4][4][4] = {};               // [msub][nsub][frag], int32

    // prologue: prefetch chunks 0,1
    stage_chunk(sb, OFF_A(0), OFF_B(0), rowBase, colBase, 0, tid);
    CP_COMMIT();
    stage_chunk(sb, OFF_A(1), OFF_B(1), rowBase, colBase, KCB, tid);
    CP_COMMIT();

    int buf = 0;
    #pragma unroll 4
    for (int c = 0; c < NCHUNK; c++) {
        if (c == NCHUNK - 1) { CP_WAIT0(); } else { CP_WAIT1(); }
        __syncthreads();

        const uint32_t aB = sb + OFF_A(buf);
        const uint32_t bB = sb + OFF_B(buf);

        // 4 k-steps of 32 int8 (32 bytes = 2 swizzled chunks) each
        #pragma unroll
        for (int kk = 0; kk < KCB; kk += 32) {
            const uint32_t ch = (uint32_t)(kk >> 4);
            uint32_t a[4][4];
            uint32_t b[2][4];            // [n-pair][(ns even:0,1)(ns odd:2,3)]
            #pragma unroll
            for (int ms = 0; ms < 4; ms++)
                ldsm4(a[ms], aB + (uint32_t)(aRow + ms * 16) * 128
                                + (((ch + aHi) ^ aXor) << 4));
            #pragma unroll
            for (int p = 0; p < 2; p++)
                ldsm4(b[p], bB + (uint32_t)(bRow + p * 16) * 128
                               + (((ch + bHi) ^ bXor) << 4));

            #pragma unroll
            for (int ms = 0; ms < 4; ms++) {
                mma_s8(acc[ms][0], a[ms], &b[0][0]);
                mma_s8(acc[ms][1], a[ms], &b[0][2]);
                mma_s8(acc[ms][2], a[ms], &b[1][0]);
                mma_s8(acc[ms][3], a[ms], &b[1][2]);
            }
        }

        // stage chunk c+2 into buffer (c+2)%3 (its last reader finished at
        // iter c-1, proven by this iteration's barrier)
        if (c + 2 < NCHUNK) {
            int nb = buf + 2; if (nb >= 3) nb -= 3;
            stage_chunk(sb, OFF_A(nb), OFF_B(nb), rowBase, colBase, (c + 2) * KCB, tid);
            CP_COMMIT();
        }
        buf = (buf == 2) ? 0 : buf + 1;
    }

    // exp, diagonal exclusion, row + column sums
    // acc = 65536 * sim  ->  scale = 10*log2(e)/65536
    const float SCALE = 14.4269504088896340736f / 65536.0f;

    float colAcc[4][2] = {};

    #pragma unroll
    for (int ms = 0; ms < 4; ms++) {
        int r0 = mBase + ms * 16 + gid;
        float s0 = 0.f, s1 = 0.f;
        #pragma unroll
        for (int ns = 0; ns < 4; ns++) {
            int c0 = nBase + ns * 8 + tig * 2;
            float v0 = fast_ex2((float)acc[ms][ns][0] * SCALE);
            float v1 = fast_ex2((float)acc[ms][ns][1] * SCALE);
            float v2 = fast_ex2((float)acc[ms][ns][2] * SCALE);
            float v3 = fast_ex2((float)acc[ms][ns][3] * SCALE);
            if (diagTile) {
                if (r0 == c0)         v0 = 0.f;
                if (r0 == c0 + 1)     v1 = 0.f;
                if (r0 + 8 == c0)     v2 = 0.f;
                if (r0 + 8 == c0 + 1) v3 = 0.f;
            }
            s0 += v0 + v1;
            s1 += v2 + v3;
            colAcc[ns][0] += v0 + v2;
            colAcc[ns][1] += v1 + v3;
        }
        s0 += __shfl_xor_sync(0xffffffffu, s0, 1);
        s0 += __shfl_xor_sync(0xffffffffu, s0, 2);
        s1 += __shfl_xor_sync(0xffffffffu, s1, 1);
        s1 += __shfl_xor_sync(0xffffffffu, s1, 2);
        if (tig == 0) {
            atomicAdd(&rs[r0], s0);
            atomicAdd(&rs[r0 + 8], s1);
        }
    }

    if (!diagTile) {
        #pragma unroll
        for (int ns = 0; ns < 4; ns++) {
            float c0v = colAcc[ns][0];
            float c1v = colAcc[ns][1];
            #pragma unroll
            for (int o = 4; o <= 16; o <<= 1) {
                c0v += __shfl_xor_sync(0xffffffffu, c0v, o);
                c1v += __shfl_xor_sync(0xffffffffu, c1v, o);
            }
            if (gid == 0) {
                int c0 = nBase + ns * 8 + tig * 2;
                atomicAdd(&cs[c0], c0v);
                atomicAdd(&cs[c0 + 1], c1v);
            }
        }
    }
    __syncthreads();

    if (tid < TILE) {
        bool inNum = ((rowBase < BIJ) == (colBase < BIJ));
        float rv = rs[tid];
        atomicAdd(&g_denom[rowBase + tid], rv);
        if (inNum) atomicAdd(&g_num[rowBase + tid], rv);
        if (!diagTile) {
            float cv = cs[tid];
            atomicAdd(&g_denom[colBase + tid], cv);
            if (inNum) atomicAdd(&g_num[colBase + tid], cv);
        }
    }
}

// ---------------------------------------------------------------------------
// Kernel 3: per-row loss and final scalar. log via MUFU lg2.
// ---------------------------------------------------------------------------
__global__ void k_loss(float* __restrict__ out) {
    const float LN2 = 0.6931471805599453f;
    int tid = threadIdx.x;
    float s = 0.f;
    for (int ii = tid; ii < SIZE; ii += 512) {
        float cntm1 = (ii < BIJ) ? (float)(BIJ - 1) : (float)(BROWS - 1);
        s += (fast_lg2(g_denom[ii]) - fast_lg2(g_num[ii]) + fast_lg2(cntm1)) * LN2;
    }
    #pragma unroll
    for (int o = 16; o; o >>= 1) s += __shfl_xor_sync(0xffffffffu, s, o);
    __shared__ float ws[16];
    if ((tid & 31) == 0) ws[tid >> 5] = s;
    __syncthreads();
    if (tid == 0) {
        float tsum = 0.f;
        #pragma unroll
        for (int w = 0; w < 16; w++) tsum += ws[w];
        out[0] = tsum / (float)SIZE;
    }
}

// ---------------------------------------------------------------------------
extern "C" void kernel_launch(void* const* d_in, const int* in_sizes, int n_in,
                              void* d_out, int out_size) {
    const float* emb_i = (const float*)d_in[0];
    const float* emb_j = (const float*)d_in[1];
    const float* emb_k = (const float*)d_in[2];
    float* out = (float*)d_out;

    cudaFuncSetAttribute(k_sim, cudaFuncAttributeMaxDynamicSharedMemorySize, SMEM_TOTAL);

    k_normalize<<<SIZE / 8, 256>>>(emb_i, emb_j, emb_k);
    k_sim<<<NBLOCKS, 256, SMEM_TOTAL>>>();
    k_loss<<<1, 512>>>(out);
}

// round 12
// speedup vs baseline: 1.2749x; 1.1011x over previous
#include <cuda_runtime.h>
#include <cuda_bf16.h>
#include <cstdint>
#include <math.h>

#define D      2048
#define BROWS  2048
#define SIZE   6144
#define BIJ    4096
#define TILE   128
#define KCB    128                    // k-elements (=bytes) per chunk, int8
#define NCHUNK (D / KCB)              // 16
#define NTILES 48
#define NBLOCKS (NTILES * (NTILES + 1) / 2)   // 1176 upper-triangle tiles

// Swizzled 128B rows: byte chunk cc (16B) of row r stored at (cc ^ (r&7))*16.
#define BUFSZ   (TILE * 128)          // 16384
// smem: A0,A1,A2,B0,B1,B2, rs(512), cs(512)
#define OFF_A(b) ((b) * BUFSZ)
#define OFF_B(b) ((3 + (b)) * BUFSZ)
#define OFF_RS  (6 * BUFSZ)
#define OFF_CS  (6 * BUFSZ + 512)
#define SMEM_TOTAL (6 * BUFSZ + 1024)

// Scratch (device globals: allocation-free per harness rules)
__device__ uint8_t g_z8[(size_t)SIZE * D];   // round(256 * normalized emb), int8
__device__ float g_denom[SIZE];
__device__ float g_num[SIZE];

__device__ __forceinline__ uint32_t smem_u32(const void* p) {
    uint32_t a;
    asm("{ .reg .u64 t; cvta.to.shared.u64 t, %1; cvt.u32.u64 %0, t; }" : "=r"(a) : "l"(p));
    return a;
}
__device__ __forceinline__ float fast_ex2(float x) {
    float y; asm("ex2.approx.ftz.f32 %0, %1;" : "=f"(y) : "f"(x)); return y;
}
__device__ __forceinline__ float fast_lg2(float x) {
    float y; asm("lg2.approx.f32 %0, %1;" : "=f"(y) : "f"(x)); return y;
}
__device__ __forceinline__ uint32_t to_s8(float x) {
    uint32_t r;
    asm("cvt.rni.sat.s8.f32 %0, %1;" : "=r"(r) : "f"(x));
    return r & 0xFFu;
}
__device__ __forceinline__ uint32_t pack4_s8(float a, float b, float c, float d) {
    return to_s8(a) | (to_s8(b) << 8) | (to_s8(c) << 16) | (to_s8(d) << 24);
}
__device__ __forceinline__ void cp16(uint32_t dst, const void* src) {
    asm volatile("cp.async.cg.shared.global [%0], [%1], 16;" :: "r"(dst), "l"(src));
}
#define CP_COMMIT()  asm volatile("cp.async.commit_group;" ::: "memory")
#define CP_WAIT1()   asm volatile("cp.async.wait_group 1;" ::: "memory")
#define CP_WAIT0()   asm volatile("cp.async.wait_group 0;" ::: "memory")

__device__ __forceinline__ void ldsm4(uint32_t* r, uint32_t addr) {
    asm volatile("ldmatrix.sync.aligned.m8n8.x4.shared.b16 {%0,%1,%2,%3}, [%4];"
                 : "=r"(r[0]), "=r"(r[1]), "=r"(r[2]), "=r"(r[3]) : "r"(addr));
}
__device__ __forceinline__ void mma_s8(int c[4], const uint32_t a[4], const uint32_t b[2]) {
    asm volatile(
        "mma.sync.aligned.m16n8k32.row.col.s32.s8.s8.s32 "
        "{%0,%1,%2,%3}, {%4,%5,%6,%7}, {%8,%9}, {%0,%1,%2,%3};"
        : "+r"(c[0]), "+r"(c[1]), "+r"(c[2]), "+r"(c[3])
        : "r"(a[0]), "r"(a[1]), "r"(a[2]), "r"(a[3]), "r"(b[0]), "r"(b[1]));
}

// ---------------------------------------------------------------------------
// Kernel 1: L2-normalize -> int8 (x256). One block (512 thr) per row, ONE
// pass: each thread holds exactly one float4 across the block reduction.
// ---------------------------------------------------------------------------
__global__ __launch_bounds__(512, 4)
void k_normalize(const float* __restrict__ e0,
                 const float* __restrict__ e1,
                 const float* __restrict__ e2) {
    const int row = blockIdx.x;
    const int tid = threadIdx.x;
    if (tid == 0) { g_denom[row] = 0.f; g_num[row] = 0.f; }

    const float* src;
    if (row < BROWS)            src = e0 + (size_t)row * D;
    else if (row < 2 * BROWS)   src = e1 + (size_t)(row - BROWS) * D;
    else                        src = e2 + (size_t)(row - 2 * BROWS) * D;

    float4 v = ((const float4*)src)[tid];
    float ss = v.x * v.x + v.y * v.y + v.z * v.z + v.w * v.w;

    #pragma unroll
    for (int o = 16; o; o >>= 1) ss += __shfl_xor_sync(0xffffffffu, ss, o);

    __shared__ float ws[16];
    __shared__ float stot;
    if ((tid & 31) == 0) ws[tid >> 5] = ss;
    __syncthreads();
    if (tid == 0) {
        float t = 0.f;
        #pragma unroll
        for (int w = 0; w < 16; w++) t += ws[w];
        stot = t;
    }
    __syncthreads();

    float inv = 256.0f / fmaxf(sqrtf(stot), 1e-12f);

    ((uint32_t*)(g_z8 + (size_t)row * D))[tid] =
        pack4_s8(v.x * inv, v.y * inv, v.z * inv, v.w * inv);
}

// ---------------------------------------------------------------------------
// Kernel 2: upper-triangle tiles, int8 mma, 3-stage cp.async pipeline,
// swizzled smem, one barrier per chunk (R8 structure, proven fastest).
// 256 threads = 8 warps, 2(M) x 4(N).
// ---------------------------------------------------------------------------
__device__ __forceinline__ void stage_chunk(uint32_t sb, uint32_t aOff, uint32_t bOff,
                                            int rowBase, int colBase, int k0, int tid) {
    #pragma unroll
    for (int it = 0; it < 4; it++) {
        int id = tid + it * 256;          // 0..1023
        int r  = id >> 3;                 // 0..127
        int cc = id & 7;                  // 16B chunk within row
        uint32_t o = (uint32_t)(r * 128 + ((cc ^ (r & 7)) << 4));
        cp16(sb + aOff + o, g_z8 + (size_t)(rowBase + r) * D + k0 + cc * 16);
        cp16(sb + bOff + o, g_z8 + (size_t)(colBase + r) * D + k0 + cc * 16);
    }
}

__global__ __launch_bounds__(256, 2)
void k_sim() {
    extern __shared__ char smem[];
    const uint32_t sb = smem_u32(smem);
    float* rs = (float*)(smem + OFF_RS);
    float* cs = (float*)(smem + OFF_CS);

    // Triangular decode: t = i*(i+1)/2 + j with j <= i; rowTile=j, colTile=i
    int t = blockIdx.x;
    int i = (int)((sqrtf(8.0f * (float)t + 1.0f) - 1.0f) * 0.5f);
    while ((i + 1) * (i + 2) / 2 <= t) i++;
    while (i * (i + 1) / 2 > t) i--;
    int j = t - i * (i + 1) / 2;

    const int rowBase = j * TILE;
    const int colBase = i * TILE;
    const bool diagTile = (i == j);

    const int tid  = threadIdx.x;
    const int wid  = tid >> 5;
    const int lane = tid & 31;
    const int mBase = (wid >> 2) * 64;   // warpM in {0,1}
    const int nBase = (wid & 3) * 32;    // warpN in {0..3}
    const int gid = lane >> 2;
    const int tig = lane & 3;

    if (tid < 2 * TILE) ((float*)(smem + OFF_RS))[tid] = 0.f;

    // ldmatrix lane addressing (swizzled)
    const int aRow = mBase + (lane & 15);          // +ms*16 preserves &7
    const uint32_t aXor = (uint32_t)(aRow & 7);
    const uint32_t aHi  = (lane & 16) ? 1u : 0u;
    const int bRow = nBase + ((lane & 16) ? 8 : 0) + (lane & 7);   // +p*16 preserves &7
    const uint32_t bXor = (uint32_t)(bRow & 7);
    const uint32_t bHi  = (lane & 8) ? 1u : 0u;

    int acc[4][4][4] = {};               // [msub][nsub][frag], int32

    // prologue: prefetch chunks 0,1
    stage_chunk(sb, OFF_A(0), OFF_B(0), rowBase, colBase, 0, tid);
    CP_COMMIT();
    stage_chunk(sb, OFF_A(1), OFF_B(1), rowBase, colBase, KCB, tid);
    CP_COMMIT();

    int buf = 0;
    #pragma unroll 4
    for (int c = 0; c < NCHUNK; c++) {
        if (c == NCHUNK - 1) { CP_WAIT0(); } else { CP_WAIT1(); }
        __syncthreads();

        const uint32_t aB = sb + OFF_A(buf);
        const uint32_t bB = sb + OFF_B(buf);

        // 4 k-steps of 32 int8 (32 bytes = 2 swizzled chunks) each
        #pragma unroll
        for (int kk = 0; kk < KCB; kk += 32) {
            const uint32_t ch = (uint32_t)(kk >> 4);
            uint32_t a[4][4];
            uint32_t b[2][4];            // [n-pair][(ns even:0,1)(ns odd:2,3)]
            #pragma unroll
            for (int ms = 0; ms < 4; ms++)
                ldsm4(a[ms], aB + (uint32_t)(aRow + ms * 16) * 128
                                + (((ch + aHi) ^ aXor) << 4));
            #pragma unroll
            for (int p = 0; p < 2; p++)
                ldsm4(b[p], bB + (uint32_t)(bRow + p * 16) * 128
                               + (((ch + bHi) ^ bXor) << 4));

            #pragma unroll
            for (int ms = 0; ms < 4; ms++) {
                mma_s8(acc[ms][0], a[ms], &b[0][0]);
                mma_s8(acc[ms][1], a[ms], &b[0][2]);
                mma_s8(acc[ms][2], a[ms], &b[1][0]);
                mma_s8(acc[ms][3], a[ms], &b[1][2]);
            }
        }

        // stage chunk c+2 into buffer (c+2)%3 (its last reader finished at
        // iter c-1, proven by this iteration's barrier)
        if (c + 2 < NCHUNK) {
            int nb = buf + 2; if (nb >= 3) nb -= 3;
            stage_chunk(sb, OFF_A(nb), OFF_B(nb), rowBase, colBase, (c + 2) * KCB, tid);
            CP_COMMIT();
        }
        buf = (buf == 2) ? 0 : buf + 1;
    }

    // exp, diagonal exclusion, row + column sums
    // acc = 65536 * sim  ->  scale = 10*log2(e)/65536
    const float SCALE = 14.4269504088896340736f / 65536.0f;

    float colAcc[4][2] = {};

    #pragma unroll
    for (int ms = 0; ms < 4; ms++) {
        int r0 = mBase + ms * 16 + gid;
        float s0 = 0.f, s1 = 0.f;
        #pragma unroll
        for (int ns = 0; ns < 4; ns++) {
            int c0 = nBase + ns * 8 + tig * 2;
            float v0 = fast_ex2((float)acc[ms][ns][0] * SCALE);
            float v1 = fast_ex2((float)acc[ms][ns][1] * SCALE);
            float v2 = fast_ex2((float)acc[ms][ns][2] * SCALE);
            float v3 = fast_ex2((float)acc[ms][ns][3] * SCALE);
            if (diagTile) {
                if (r0 == c0)         v0 = 0.f;
                if (r0 == c0 + 1)     v1 = 0.f;
                if (r0 + 8 == c0)     v2 = 0.f;
                if (r0 + 8 == c0 + 1) v3 = 0.f;
            }
            s0 += v0 + v1;
            s1 += v2 + v3;
            colAcc[ns][0] += v0 + v2;
            colAcc[ns][1] += v1 + v3;
        }
        s0 += __shfl_xor_sync(0xffffffffu, s0, 1);
        s0 += __shfl_xor_sync(0xffffffffu, s0, 2);
        s1 += __shfl_xor_sync(0xffffffffu, s1, 1);
        s1 += __shfl_xor_sync(0xffffffffu, s1, 2);
        if (tig == 0) {
            atomicAdd(&rs[r0], s0);
            atomicAdd(&rs[r0 + 8], s1);
        }
    }

    if (!diagTile) {
        #pragma unroll
        for (int ns = 0; ns < 4; ns++) {
            float c0v = colAcc[ns][0];
            float c1v = colAcc[ns][1];
            #pragma unroll
            for (int o = 4; o <= 16; o <<= 1) {
                c0v += __shfl_xor_sync(0xffffffffu, c0v, o);
                c1v += __shfl_xor_sync(0xffffffffu, c1v, o);
            }
            if (gid == 0) {
                int c0 = nBase + ns * 8 + tig * 2;
                atomicAdd(&cs[c0], c0v);
                atomicAdd(&cs[c0 + 1], c1v);
            }
        }
    }
    __syncthreads();

    if (tid < TILE) {
        bool inNum = ((rowBase < BIJ) == (colBase < BIJ));
        float rv = rs[tid];
        atomicAdd(&g_denom[rowBase + tid], rv);
        if (inNum) atomicAdd(&g_num[rowBase + tid], rv);
        if (!diagTile) {
            float cv = cs[tid];
            atomicAdd(&g_denom[colBase + tid], cv);
            if (inNum) atomicAdd(&g_num[colBase + tid], cv);
        }
    }
}

// ---------------------------------------------------------------------------
// Kernel 3: per-row loss and final scalar. log via MUFU lg2.
// ---------------------------------------------------------------------------
__global__ void k_loss(float* __restrict__ out) {
    const float LN2 = 0.6931471805599453f;
    int tid = threadIdx.x;
    float s = 0.f;
    for (int ii = tid; ii < SIZE; ii += 512) {
        float cntm1 = (ii < BIJ) ? (float)(BIJ - 1) : (float)(BROWS - 1);
        s += (fast_lg2(g_denom[ii]) - fast_lg2(g_num[ii]) + fast_lg2(cntm1)) * LN2;
    }
    #pragma unroll
    for (int o = 16; o; o >>= 1) s += __shfl_xor_sync(0xffffffffu, s, o);
    __shared__ float ws[16];
    if ((tid & 31) == 0) ws[tid >> 5] = s;
    __syncthreads();
    if (tid == 0) {
        float tsum = 0.f;
        #pragma unroll
        for (int w = 0; w < 16; w++) tsum += ws[w];
        out[0] = tsum / (float)SIZE;
    }
}

// ---------------------------------------------------------------------------
extern "C" void kernel_launch(void* const* d_in, const int* in_sizes, int n_in,
                              void* d_out, int out_size) {
    const float* emb_i = (const float*)d_in[0];
    const float* emb_j = (const float*)d_in[1];
    const float* emb_k = (const float*)d_in[2];
    float* out = (float*)d_out;

    cudaFuncSetAttribute(k_sim, cudaFuncAttributeMaxDynamicSharedMemorySize, SMEM_TOTAL);

    k_normalize<<<SIZE, 512>>>(emb_i, emb_j, emb_k);
    k_sim<<<NBLOCKS, 256, SMEM_TOTAL>>>();
    k_loss<<<1, 512>>>(out);
}

// round 13
// speedup vs baseline: 1.3431x; 1.0535x over previous
#include <cuda_runtime.h>
#include <cuda_bf16.h>
#include <cstdint>
#include <math.h>

#define D      2048
#define BROWS  2048
#define SIZE   6144
#define BIJ    4096
#define TILE   128
#define KCB    128                    // k-elements (=bytes) per chunk, int8
#define NCHUNK (D / KCB)              // 16
#define NTILES 48
#define NBLOCKS (NTILES * (NTILES + 1) / 2)   // 1176 upper-triangle tiles

// Swizzled 128B rows: byte chunk cc (16B) of row r stored at (cc ^ (r&7))*16.
#define BUFSZ   (TILE * 128)          // 16384
// smem: A0,A1,A2,B0,B1,B2, rs(512), cs(512)
#define OFF_A(b) ((b) * BUFSZ)
#define OFF_B(b) ((3 + (b)) * BUFSZ)
#define OFF_RS  (6 * BUFSZ)
#define OFF_CS  (6 * BUFSZ + 512)
#define SMEM_TOTAL (6 * BUFSZ + 1024)

// Scratch (device globals: allocation-free per harness rules)
__device__ uint8_t g_z8[(size_t)SIZE * D];   // round(256 * normalized emb), int8
__device__ float g_denom[SIZE];
__device__ float g_num[SIZE];

__device__ __forceinline__ uint32_t smem_u32(const void* p) {
    uint32_t a;
    asm("{ .reg .u64 t; cvta.to.shared.u64 t, %1; cvt.u32.u64 %0, t; }" : "=r"(a) : "l"(p));
    return a;
}
__device__ __forceinline__ float fast_ex2(float x) {
    float y; asm("ex2.approx.ftz.f32 %0, %1;" : "=f"(y) : "f"(x)); return y;
}
__device__ __forceinline__ float fast_lg2(float x) {
    float y; asm("lg2.approx.f32 %0, %1;" : "=f"(y) : "f"(x)); return y;
}
__device__ __forceinline__ uint32_t to_s8(float x) {
    uint32_t r;
    asm("cvt.rni.sat.s8.f32 %0, %1;" : "=r"(r) : "f"(x));
    return r & 0xFFu;
}
__device__ __forceinline__ uint32_t pack4_s8(float a, float b, float c, float d) {
    return to_s8(a) | (to_s8(b) << 8) | (to_s8(c) << 16) | (to_s8(d) << 24);
}
__device__ __forceinline__ void cp16(uint32_t dst, const void* src) {
    asm volatile("cp.async.cg.shared.global [%0], [%1], 16;" :: "r"(dst), "l"(src));
}
#define CP_COMMIT()  asm volatile("cp.async.commit_group;" ::: "memory")
#define CP_WAIT1()   asm volatile("cp.async.wait_group 1;" ::: "memory")
#define CP_WAIT0()   asm volatile("cp.async.wait_group 0;" ::: "memory")

__device__ __forceinline__ void ldsm4(uint32_t* r, uint32_t addr) {
    asm volatile("ldmatrix.sync.aligned.m8n8.x4.shared.b16 {%0,%1,%2,%3}, [%4];"
                 : "=r"(r[0]), "=r"(r[1]), "=r"(r[2]), "=r"(r[3]) : "r"(addr));
}
__device__ __forceinline__ void mma_s8(int c[4], const uint32_t a[4], const uint32_t b[2]) {
    asm volatile(
        "mma.sync.aligned.m16n8k32.row.col.s32.s8.s8.s32 "
        "{%0,%1,%2,%3}, {%4,%5,%6,%7}, {%8,%9}, {%0,%1,%2,%3};"
        : "+r"(c[0]), "+r"(c[1]), "+r"(c[2]), "+r"(c[3])
        : "r"(a[0]), "r"(a[1]), "r"(a[2]), "r"(a[3]), "r"(b[0]), "r"(b[1]));
}

// ---------------------------------------------------------------------------
// Kernel 1: L2-normalize -> int8 (x256). TWO warps per row (64 thr/row),
// one pass, one block barrier. Block 256 = 4 rows; grid = 1536.
// ---------------------------------------------------------------------------
__global__ __launch_bounds__(256, 6)
void k_normalize(const float* __restrict__ e0,
                 const float* __restrict__ e1,
                 const float* __restrict__ e2) {
    const int tid = threadIdx.x;
    const int wid = tid >> 5;            // 0..7
    const int t   = tid & 63;            // thread-in-row
    const int row = blockIdx.x * 4 + (tid >> 6);
    if (t == 0) { g_denom[row] = 0.f; g_num[row] = 0.f; }

    const float* src;
    if (row < BROWS)            src = e0 + (size_t)row * D;
    else if (row < 2 * BROWS)   src = e1 + (size_t)(row - BROWS) * D;
    else                        src = e2 + (size_t)(row - 2 * BROWS) * D;
    const float4* s4 = (const float4*)src;

    float4 v[8];
    float ss = 0.f;
    #pragma unroll
    for (int it = 0; it < 8; it++) {
        v[it] = s4[t + 64 * it];
        ss += v[it].x * v[it].x + v[it].y * v[it].y
            + v[it].z * v[it].z + v[it].w * v[it].w;
    }

    #pragma unroll
    for (int o = 16; o; o >>= 1) ss += __shfl_xor_sync(0xffffffffu, ss, o);

    __shared__ float ws[8];
    if ((tid & 31) == 0) ws[wid] = ss;
    __syncthreads();
    float inv = 256.0f / fmaxf(sqrtf(ss + ws[wid ^ 1]), 1e-12f);

    uint32_t* d32 = (uint32_t*)(g_z8 + (size_t)row * D);
    #pragma unroll
    for (int it = 0; it < 8; it++) {
        d32[t + 64 * it] =
            pack4_s8(v[it].x * inv, v[it].y * inv, v[it].z * inv, v[it].w * inv);
    }
}

// ---------------------------------------------------------------------------
// Kernel 2: upper-triangle tiles, int8 mma, 3-stage cp.async pipeline,
// swizzled smem, one barrier per chunk (R8 structure, proven fastest).
// 256 threads = 8 warps, 2(M) x 4(N).
// ---------------------------------------------------------------------------
__device__ __forceinline__ void stage_chunk(uint32_t sb, uint32_t aOff, uint32_t bOff,
                                            int rowBase, int colBase, int k0, int tid) {
    #pragma unroll
    for (int it = 0; it < 4; it++) {
        int id = tid + it * 256;          // 0..1023
        int r  = id >> 3;                 // 0..127
        int cc = id & 7;                  // 16B chunk within row
        uint32_t o = (uint32_t)(r * 128 + ((cc ^ (r & 7)) << 4));
        cp16(sb + aOff + o, g_z8 + (size_t)(rowBase + r) * D + k0 + cc * 16);
        cp16(sb + bOff + o, g_z8 + (size_t)(colBase + r) * D + k0 + cc * 16);
    }
}

__global__ __launch_bounds__(256, 2)
void k_sim() {
    extern __shared__ char smem[];
    const uint32_t sb = smem_u32(smem);
    float* rs = (float*)(smem + OFF_RS);
    float* cs = (float*)(smem + OFF_CS);

    // Triangular decode: t = i*(i+1)/2 + j with j <= i; rowTile=j, colTile=i
    int t = blockIdx.x;
    int i = (int)((sqrtf(8.0f * (float)t + 1.0f) - 1.0f) * 0.5f);
    while ((i + 1) * (i + 2) / 2 <= t) i++;
    while (i * (i + 1) / 2 > t) i--;
    int j = t - i * (i + 1) / 2;

    const int rowBase = j * TILE;
    const int colBase = i * TILE;
    const bool diagTile = (i == j);

    const int tid  = threadIdx.x;
    const int wid  = tid >> 5;
    const int lane = tid & 31;
    const int mBase = (wid >> 2) * 64;   // warpM in {0,1}
    const int nBase = (wid & 3) * 32;    // warpN in {0..3}
    const int gid = lane >> 2;
    const int tig = lane & 3;

    if (tid < 2 * TILE) ((float*)(smem + OFF_RS))[tid] = 0.f;

    // ldmatrix lane addressing (swizzled)
    const int aRow = mBase + (lane & 15);          // +ms*16 preserves &7
    const uint32_t aXor = (uint32_t)(aRow & 7);
    const uint32_t aHi  = (lane & 16) ? 1u : 0u;
    const int bRow = nBase + ((lane & 16) ? 8 : 0) + (lane & 7);   // +p*16 preserves &7
    const uint32_t bXor = (uint32_t)(bRow & 7);
    const uint32_t bHi  = (lane & 8) ? 1u : 0u;

    int acc[4][4][4] = {};               // [msub][nsub][frag], int32

    // prologue: prefetch chunks 0,1
    stage_chunk(sb, OFF_A(0), OFF_B(0), rowBase, colBase, 0, tid);
    CP_COMMIT();
    stage_chunk(sb, OFF_A(1), OFF_B(1), rowBase, colBase, KCB, tid);
    CP_COMMIT();

    int buf = 0;
    #pragma unroll 4
    for (int c = 0; c < NCHUNK; c++) {
        if (c == NCHUNK - 1) { CP_WAIT0(); } else { CP_WAIT1(); }
        __syncthreads();

        const uint32_t aB = sb + OFF_A(buf);
        const uint32_t bB = sb + OFF_B(buf);

        // 4 k-steps of 32 int8 (32 bytes = 2 swizzled chunks) each
        #pragma unroll
        for (int kk = 0; kk < KCB; kk += 32) {
            const uint32_t ch = (uint32_t)(kk >> 4);
            uint32_t a[4][4];
            uint32_t b[2][4];            // [n-pair][(ns even:0,1)(ns odd:2,3)]
            #pragma unroll
            for (int ms = 0; ms < 4; ms++)
                ldsm4(a[ms], aB + (uint32_t)(aRow + ms * 16) * 128
                                + (((ch + aHi) ^ aXor) << 4));
            #pragma unroll
            for (int p = 0; p < 2; p++)
                ldsm4(b[p], bB + (uint32_t)(bRow + p * 16) * 128
                               + (((ch + bHi) ^ bXor) << 4));

            #pragma unroll
            for (int ms = 0; ms < 4; ms++) {
                mma_s8(acc[ms][0], a[ms], &b[0][0]);
                mma_s8(acc[ms][1], a[ms], &b[0][2]);
                mma_s8(acc[ms][2], a[ms], &b[1][0]);
                mma_s8(acc[ms][3], a[ms], &b[1][2]);
            }
        }

        // stage chunk c+2 into buffer (c+2)%3 (its last reader finished at
        // iter c-1, proven by this iteration's barrier)
        if (c + 2 < NCHUNK) {
            int nb = buf + 2; if (nb >= 3) nb -= 3;
            stage_chunk(sb, OFF_A(nb), OFF_B(nb), rowBase, colBase, (c + 2) * KCB, tid);
            CP_COMMIT();
        }
        buf = (buf == 2) ? 0 : buf + 1;
    }

    // exp, diagonal exclusion, row + column sums
    // acc = 65536 * sim  ->  scale = 10*log2(e)/65536
    const float SCALE = 14.4269504088896340736f / 65536.0f;

    float colAcc[4][2] = {};

    #pragma unroll
    for (int ms = 0; ms < 4; ms++) {
        int r0 = mBase + ms * 16 + gid;
        float s0 = 0.f, s1 = 0.f;
        #pragma unroll
        for (int ns = 0; ns < 4; ns++) {
            int c0 = nBase + ns * 8 + tig * 2;
            float v0 = fast_ex2((float)acc[ms][ns][0] * SCALE);
            float v1 = fast_ex2((float)acc[ms][ns][1] * SCALE);
            float v2 = fast_ex2((float)acc[ms][ns][2] * SCALE);
            float v3 = fast_ex2((float)acc[ms][ns][3] * SCALE);
            if (diagTile) {
                if (r0 == c0)         v0 = 0.f;
                if (r0 == c0 + 1)     v1 = 0.f;
                if (r0 + 8 == c0)     v2 = 0.f;
                if (r0 + 8 == c0 + 1) v3 = 0.f;
            }
            s0 += v0 + v1;
            s1 += v2 + v3;
            colAcc[ns][0] += v0 + v2;
            colAcc[ns][1] += v1 + v3;
        }
        s0 += __shfl_xor_sync(0xffffffffu, s0, 1);
        s0 += __shfl_xor_sync(0xffffffffu, s0, 2);
        s1 += __shfl_xor_sync(0xffffffffu, s1, 1);
        s1 += __shfl_xor_sync(0xffffffffu, s1, 2);
        if (tig == 0) {
            atomicAdd(&rs[r0], s0);
            atomicAdd(&rs[r0 + 8], s1);
        }
    }

    if (!diagTile) {
        #pragma unroll
        for (int ns = 0; ns < 4; ns++) {
            float c0v = colAcc[ns][0];
            float c1v = colAcc[ns][1];
            #pragma unroll
            for (int o = 4; o <= 16; o <<= 1) {
                c0v += __shfl_xor_sync(0xffffffffu, c0v, o);
                c1v += __shfl_xor_sync(0xffffffffu, c1v, o);
            }
            if (gid == 0) {
                int c0 = nBase + ns * 8 + tig * 2;
                atomicAdd(&cs[c0], c0v);
                atomicAdd(&cs[c0 + 1], c1v);
            }
        }
    }
    __syncthreads();

    if (tid < TILE) {
        bool inNum = ((rowBase < BIJ) == (colBase < BIJ));
        float rv = rs[tid];
        atomicAdd(&g_denom[rowBase + tid], rv);
        if (inNum) atomicAdd(&g_num[rowBase + tid], rv);
        if (!diagTile) {
            float cv = cs[tid];
            atomicAdd(&g_denom[colBase + tid], cv);
            if (inNum) atomicAdd(&g_num[colBase + tid], cv);
        }
    }
}

// ---------------------------------------------------------------------------
// Kernel 3: per-row loss and final scalar. log via MUFU lg2.
// ---------------------------------------------------------------------------
__global__ void k_loss(float* __restrict__ out) {
    const float LN2 = 0.6931471805599453f;
    int tid = threadIdx.x;
    float s = 0.f;
    for (int ii = tid; ii < SIZE; ii += 512) {
        float cntm1 = (ii < BIJ) ? (float)(BIJ - 1) : (float)(BROWS - 1);
        s += (fast_lg2(g_denom[ii]) - fast_lg2(g_num[ii]) + fast_lg2(cntm1)) * LN2;
    }
    #pragma unroll
    for (int o = 16; o; o >>= 1) s += __shfl_xor_sync(0xffffffffu, s, o);
    __shared__ float ws[16];
    if ((tid & 31) == 0) ws[tid >> 5] = s;
    __syncthreads();
    if (tid == 0) {
        float tsum = 0.f;
        #pragma unroll
        for (int w = 0; w < 16; w++) tsum += ws[w];
        out[0] = tsum / (float)SIZE;
    }
}

// ---------------------------------------------------------------------------
extern "C" void kernel_launch(void* const* d_in, const int* in_sizes, int n_in,
                              void* d_out, int out_size) {
    const float* emb_i = (const float*)d_in[0];
    const float* emb_j = (const float*)d_in[1];
    const float* emb_k = (const float*)d_in[2];
    float* out = (float*)d_out;

    cudaFuncSetAttribute(k_sim, cudaFuncAttributeMaxDynamicSharedMemorySize, SMEM_TOTAL);

    k_normalize<<<SIZE / 4, 256>>>(emb_i, emb_j, emb_k);
    k_sim<<<NBLOCKS, 256, SMEM_TOTAL>>>();
    k_loss<<<1, 512>>>(out);
}

// round 14
// speedup vs baseline: 1.3497x; 1.0049x over previous
#include <cuda_runtime.h>
#include <cuda_bf16.h>
#include <cstdint>
#include <math.h>

#define D      2048
#define BROWS  2048
#define SIZE   6144
#define BIJ    4096
#define TILE   128
#define KCB    128                    // k-elements (=bytes) per chunk, int8
#define NCHUNK (D / KCB)              // 16
#define NTILES 48
#define NBLOCKS (NTILES * (NTILES + 1) / 2)   // 1176 upper-triangle tiles

// Swizzled 128B rows: byte chunk cc (16B) of row r stored at (cc ^ (r&7))*16.
#define BUFSZ   (TILE * 128)          // 16384
// smem: A0,A1,A2,B0,B1,B2, rs(512), cs(512)
#define OFF_A(b) ((b) * BUFSZ)
#define OFF_B(b) ((3 + (b)) * BUFSZ)
#define OFF_RS  (6 * BUFSZ)
#define OFF_CS  (6 * BUFSZ + 512)
#define SMEM_TOTAL (6 * BUFSZ + 1024)

// Scratch (device globals: allocation-free per harness rules)
__device__ uint8_t g_z8[(size_t)SIZE * D];   // round(256 * normalized emb), int8
__device__ float g_denom[SIZE];
__device__ float g_num[SIZE];

__device__ __forceinline__ uint32_t smem_u32(const void* p) {
    uint32_t a;
    asm("{ .reg .u64 t; cvta.to.shared.u64 t, %1; cvt.u32.u64 %0, t; }" : "=r"(a) : "l"(p));
    return a;
}
__device__ __forceinline__ float fast_ex2(float x) {
    float y; asm("ex2.approx.ftz.f32 %0, %1;" : "=f"(y) : "f"(x)); return y;
}
__device__ __forceinline__ float fast_lg2(float x) {
    float y; asm("lg2.approx.f32 %0, %1;" : "=f"(y) : "f"(x)); return y;
}
__device__ __forceinline__ uint32_t to_s8(float x) {
    uint32_t r;
    asm("cvt.rni.sat.s8.f32 %0, %1;" : "=r"(r) : "f"(x));
    return r & 0xFFu;
}
__device__ __forceinline__ uint32_t pack4_s8(float a, float b, float c, float d) {
    return to_s8(a) | (to_s8(b) << 8) | (to_s8(c) << 16) | (to_s8(d) << 24);
}
__device__ __forceinline__ void cp16(uint32_t dst, const void* src) {
    asm volatile("cp.async.cg.shared.global [%0], [%1], 16;" :: "r"(dst), "l"(src));
}
#define CP_COMMIT()  asm volatile("cp.async.commit_group;" ::: "memory")
#define CP_WAIT1()   asm volatile("cp.async.wait_group 1;" ::: "memory")
#define CP_WAIT0()   asm volatile("cp.async.wait_group 0;" ::: "memory")

__device__ __forceinline__ void ldsm4(uint32_t* r, uint32_t addr) {
    asm volatile("ldmatrix.sync.aligned.m8n8.x4.shared.b16 {%0,%1,%2,%3}, [%4];"
                 : "=r"(r[0]), "=r"(r[1]), "=r"(r[2]), "=r"(r[3]) : "r"(addr));
}
__device__ __forceinline__ void mma_s8(int c[4], const uint32_t a[4], const uint32_t b[2]) {
    asm volatile(
        "mma.sync.aligned.m16n8k32.row.col.s32.s8.s8.s32 "
        "{%0,%1,%2,%3}, {%4,%5,%6,%7}, {%8,%9}, {%0,%1,%2,%3};"
        : "+r"(c[0]), "+r"(c[1]), "+r"(c[2]), "+r"(c[3])
        : "r"(a[0]), "r"(a[1]), "r"(a[2]), "r"(a[3]), "r"(b[0]), "r"(b[1]));
}

// ---------------------------------------------------------------------------
// Kernel 1: L2-normalize -> int8 (x256). One warp per row, full retention,
// zero block barriers (measured-best variant: 12.9us).
// ---------------------------------------------------------------------------
__global__ void k_normalize(const float* __restrict__ e0,
                            const float* __restrict__ e1,
                            const float* __restrict__ e2) {
    const int lane = threadIdx.x & 31;
    const int row  = blockIdx.x * 8 + (threadIdx.x >> 5);
    if (lane == 0) { g_denom[row] = 0.f; g_num[row] = 0.f; }

    const float* src;
    if (row < BROWS)            src = e0 + (size_t)row * D;
    else if (row < 2 * BROWS)   src = e1 + (size_t)(row - BROWS) * D;
    else                        src = e2 + (size_t)(row - 2 * BROWS) * D;
    const float4* s4 = (const float4*)src;

    float4 v[16];
    float ss = 0.f;
    #pragma unroll
    for (int it = 0; it < 16; it++) {
        v[it] = s4[lane + 32 * it];
        ss += v[it].x * v[it].x + v[it].y * v[it].y
            + v[it].z * v[it].z + v[it].w * v[it].w;
    }

    #pragma unroll
    for (int o = 16; o; o >>= 1) ss += __shfl_xor_sync(0xffffffffu, ss, o);

    float inv = 256.0f / fmaxf(sqrtf(ss), 1e-12f);

    uint32_t* d32 = (uint32_t*)(g_z8 + (size_t)row * D);
    #pragma unroll
    for (int it = 0; it < 16; it++) {
        d32[lane + 32 * it] =
            pack4_s8(v[it].x * inv, v[it].y * inv, v[it].z * inv, v[it].w * inv);
    }
}

// ---------------------------------------------------------------------------
// Kernel 2: upper-triangle tiles, int8 mma, 3-stage cp.async pipeline,
// swizzled smem, one barrier per chunk (R8 structure, proven fastest).
// 256 threads = 8 warps, 2(M) x 4(N).
// ---------------------------------------------------------------------------
__device__ __forceinline__ void stage_chunk(uint32_t sb, uint32_t aOff, uint32_t bOff,
                                            int rowBase, int colBase, int k0, int tid) {
    #pragma unroll
    for (int it = 0; it < 4; it++) {
        int id = tid + it * 256;          // 0..1023
        int r  = id >> 3;                 // 0..127
        int cc = id & 7;                  // 16B chunk within row
        uint32_t o = (uint32_t)(r * 128 + ((cc ^ (r & 7)) << 4));
        cp16(sb + aOff + o, g_z8 + (size_t)(rowBase + r) * D + k0 + cc * 16);
        cp16(sb + bOff + o, g_z8 + (size_t)(colBase + r) * D + k0 + cc * 16);
    }
}

__global__ __launch_bounds__(256, 2)
void k_sim() {
    extern __shared__ char smem[];
    const uint32_t sb = smem_u32(smem);
    float* rs = (float*)(smem + OFF_RS);
    float* cs = (float*)(smem + OFF_CS);

    // Triangular decode: t = i*(i+1)/2 + j with j <= i; rowTile=j, colTile=i
    int t = blockIdx.x;
    int i = (int)((sqrtf(8.0f * (float)t + 1.0f) - 1.0f) * 0.5f);
    while ((i + 1) * (i + 2) / 2 <= t) i++;
    while (i * (i + 1) / 2 > t) i--;
    int j = t - i * (i + 1) / 2;

    const int rowBase = j * TILE;
    const int colBase = i * TILE;
    const bool diagTile = (i == j);

    const int tid  = threadIdx.x;
    const int wid  = tid >> 5;
    const int lane = tid & 31;
    const int mBase = (wid >> 2) * 64;   // warpM in {0,1}
    const int nBase = (wid & 3) * 32;    // warpN in {0..3}
    const int gid = lane >> 2;
    const int tig = lane & 3;

    if (tid < 2 * TILE) ((float*)(smem + OFF_RS))[tid] = 0.f;

    // ldmatrix lane addressing (swizzled)
    const int aRow = mBase + (lane & 15);          // +ms*16 preserves &7
    const uint32_t aXor = (uint32_t)(aRow & 7);
    const uint32_t aHi  = (lane & 16) ? 1u : 0u;
    const int bRow = nBase + ((lane & 16) ? 8 : 0) + (lane & 7);   // +p*16 preserves &7
    const uint32_t bXor = (uint32_t)(bRow & 7);
    const uint32_t bHi  = (lane & 8) ? 1u : 0u;

    int acc[4][4][4] = {};               // [msub][nsub][frag], int32

    // prologue: prefetch chunks 0,1
    stage_chunk(sb, OFF_A(0), OFF_B(0), rowBase, colBase, 0, tid);
    CP_COMMIT();
    stage_chunk(sb, OFF_A(1), OFF_B(1), rowBase, colBase, KCB, tid);
    CP_COMMIT();

    int buf = 0;
    #pragma unroll 4
    for (int c = 0; c < NCHUNK; c++) {
        if (c == NCHUNK - 1) { CP_WAIT0(); } else { CP_WAIT1(); }
        __syncthreads();

        const uint32_t aB = sb + OFF_A(buf);
        const uint32_t bB = sb + OFF_B(buf);

        // 4 k-steps of 32 int8 (32 bytes = 2 swizzled chunks) each
        #pragma unroll
        for (int kk = 0; kk < KCB; kk += 32) {
            const uint32_t ch = (uint32_t)(kk >> 4);
            uint32_t a[4][4];
            uint32_t b[2][4];            // [n-pair][(ns even:0,1)(ns odd:2,3)]
            #pragma unroll
            for (int ms = 0; ms < 4; ms++)
                ldsm4(a[ms], aB + (uint32_t)(aRow + ms * 16) * 128
                                + (((ch + aHi) ^ aXor) << 4));
            #pragma unroll
            for (int p = 0; p < 2; p++)
                ldsm4(b[p], bB + (uint32_t)(bRow + p * 16) * 128
                               + (((ch + bHi) ^ bXor) << 4));

            #pragma unroll
            for (int ms = 0; ms < 4; ms++) {
                mma_s8(acc[ms][0], a[ms], &b[0][0]);
                mma_s8(acc[ms][1], a[ms], &b[0][2]);
                mma_s8(acc[ms][2], a[ms], &b[1][0]);
                mma_s8(acc[ms][3], a[ms], &b[1][2]);
            }
        }

        // stage chunk c+2 into buffer (c+2)%3 (its last reader finished at
        // iter c-1, proven by this iteration's barrier)
        if (c + 2 < NCHUNK) {
            int nb = buf + 2; if (nb >= 3) nb -= 3;
            stage_chunk(sb, OFF_A(nb), OFF_B(nb), rowBase, colBase, (c + 2) * KCB, tid);
            CP_COMMIT();
        }
        buf = (buf == 2) ? 0 : buf + 1;
    }

    // exp, diagonal exclusion, row + column sums
    // acc = 65536 * sim  ->  scale = 10*log2(e)/65536
    const float SCALE = 14.4269504088896340736f / 65536.0f;

    float colAcc[4][2] = {};

    #pragma unroll
    for (int ms = 0; ms < 4; ms++) {
        int r0 = mBase + ms * 16 + gid;
        float s0 = 0.f, s1 = 0.f;
        #pragma unroll
        for (int ns = 0; ns < 4; ns++) {
            int c0 = nBase + ns * 8 + tig * 2;
            float v0 = fast_ex2((float)acc[ms][ns][0] * SCALE);
            float v1 = fast_ex2((float)acc[ms][ns][1] * SCALE);
            float v2 = fast_ex2((float)acc[ms][ns][2] * SCALE);
            float v3 = fast_ex2((float)acc[ms][ns][3] * SCALE);
            if (diagTile) {
                if (r0 == c0)         v0 = 0.f;
                if (r0 == c0 + 1)     v1 = 0.f;
                if (r0 + 8 == c0)     v2 = 0.f;
                if (r0 + 8 == c0 + 1) v3 = 0.f;
            }
            s0 += v0 + v1;
            s1 += v2 + v3;
            colAcc[ns][0] += v0 + v2;
            colAcc[ns][1] += v1 + v3;
        }
        s0 += __shfl_xor_sync(0xffffffffu, s0, 1);
        s0 += __shfl_xor_sync(0xffffffffu, s0, 2);
        s1 += __shfl_xor_sync(0xffffffffu, s1, 1);
        s1 += __shfl_xor_sync(0xffffffffu, s1, 2);
        if (tig == 0) {
            atomicAdd(&rs[r0], s0);
            atomicAdd(&rs[r0 + 8], s1);
        }
    }

    if (!diagTile) {
        #pragma unroll
        for (int ns = 0; ns < 4; ns++) {
            float c0v = colAcc[ns][0];
            float c1v = colAcc[ns][1];
            #pragma unroll
            for (int o = 4; o <= 16; o <<= 1) {
                c0v += __shfl_xor_sync(0xffffffffu, c0v, o);
                c1v += __shfl_xor_sync(0xffffffffu, c1v, o);
            }
            if (gid == 0) {
                int c0 = nBase + ns * 8 + tig * 2;
                atomicAdd(&cs[c0], c0v);
                atomicAdd(&cs[c0 + 1], c1v);
            }
        }
    }
    __syncthreads();

    if (tid < TILE) {
        bool inNum = ((rowBase < BIJ) == (colBase < BIJ));
        float rv = rs[tid];
        atomicAdd(&g_denom[rowBase + tid], rv);
        if (inNum) atomicAdd(&g_num[rowBase + tid], rv);
        if (!diagTile) {
            float cv = cs[tid];
            atomicAdd(&g_denom[colBase + tid], cv);
            if (inNum) atomicAdd(&g_num[colBase + tid], cv);
        }
    }
}

// ---------------------------------------------------------------------------
// Kernel 3: per-row loss and final scalar. log via MUFU lg2.
// ---------------------------------------------------------------------------
__global__ void k_loss(float* __restrict__ out) {
    const float LN2 = 0.6931471805599453f;
    int tid = threadIdx.x;
    float s = 0.f;
    for (int ii = tid; ii < SIZE; ii += 512) {
        float cntm1 = (ii < BIJ) ? (float)(BIJ - 1) : (float)(BROWS - 1);
        s += (fast_lg2(g_denom[ii]) - fast_lg2(g_num[ii]) + fast_lg2(cntm1)) * LN2;
    }
    #pragma unroll
    for (int o = 16; o; o >>= 1) s += __shfl_xor_sync(0xffffffffu, s, o);
    __shared__ float ws[16];
    if ((tid & 31) == 0) ws[tid >> 5] = s;
    __syncthreads();
    if (tid == 0) {
        float tsum = 0.f;
        #pragma unroll
        for (int w = 0; w < 16; w++) tsum += ws[w];
        out[0] = tsum / (float)SIZE;
    }
}

// ---------------------------------------------------------------------------
extern "C" void kernel_launch(void* const* d_in, const int* in_sizes, int n_in,
                              void* d_out, int out_size) {
    const float* emb_i = (const float*)d_in[0];
    const float* emb_j = (const float*)d_in[1];
    const float* emb_k = (const float*)d_in[2];
    float* out = (float*)d_out;

    cudaFuncSetAttribute(k_sim, cudaFuncAttributeMaxDynamicSharedMemorySize, SMEM_TOTAL);

    k_normalize<<<SIZE / 8, 256>>>(emb_i, emb_j, emb_k);
    k_sim<<<NBLOCKS, 256, SMEM_TOTAL>>>();
    k_loss<<<1, 512>>>(out);
}

// round 15
// speedup vs baseline: 1.5071x; 1.1166x over previous
#include <cuda_runtime.h>
#include <cuda_bf16.h>
#include <cstdint>
#include <math.h>

#define D      2048
#define BROWS  2048
#define SIZE   6144
#define BIJ    4096
#define TILE   128
#define KCB    128                    // k-elements (=bytes) per chunk, int8
#define NCHUNK (D / KCB)              // 16
#define NTILES 48
#define NBLOCKS (NTILES * (NTILES + 1) / 2)   // 1176 upper-triangle tiles

// Swizzled 128B rows: byte chunk cc (16B) of row r stored at (cc ^ (r&7))*16.
#define BUFSZ   (TILE * 128)          // 16384
// smem: A0,A1,A2,B0,B1,B2, rs(512), cs(512)
#define OFF_A(b) ((b) * BUFSZ)
#define OFF_B(b) ((3 + (b)) * BUFSZ)
#define OFF_RS  (6 * BUFSZ)
#define OFF_CS  (6 * BUFSZ + 512)
#define SMEM_TOTAL (6 * BUFSZ + 1024)

// Scratch (device globals: allocation-free per harness rules)
__device__ uint8_t g_z8[(size_t)SIZE * D];   // round(256 * normalized emb), int8
__device__ float g_denom[SIZE];
__device__ float g_num[SIZE];

__device__ __forceinline__ uint32_t smem_u32(const void* p) {
    uint32_t a;
    asm("{ .reg .u64 t; cvta.to.shared.u64 t, %1; cvt.u32.u64 %0, t; }" : "=r"(a) : "l"(p));
    return a;
}
__device__ __forceinline__ float fast_ex2(float x) {
    float y; asm("ex2.approx.ftz.f32 %0, %1;" : "=f"(y) : "f"(x)); return y;
}
__device__ __forceinline__ float fast_lg2(float x) {
    float y; asm("lg2.approx.f32 %0, %1;" : "=f"(y) : "f"(x)); return y;
}
__device__ __forceinline__ uint32_t to_s8(float x) {
    uint32_t r;
    asm("cvt.rni.sat.s8.f32 %0, %1;" : "=r"(r) : "f"(x));
    return r & 0xFFu;
}
__device__ __forceinline__ uint32_t pack4_s8(float a, float b, float c, float d) {
    return to_s8(a) | (to_s8(b) << 8) | (to_s8(c) << 16) | (to_s8(d) << 24);
}
__device__ __forceinline__ void cp16(uint32_t dst, const void* src) {
    asm volatile("cp.async.cg.shared.global [%0], [%1], 16;" :: "r"(dst), "l"(src));
}
#define CP_COMMIT()  asm volatile("cp.async.commit_group;" ::: "memory")
#define CP_WAIT1()   asm volatile("cp.async.wait_group 1;" ::: "memory")
#define CP_WAIT0()   asm volatile("cp.async.wait_group 0;" ::: "memory")

__device__ __forceinline__ void ldsm4(uint32_t* r, uint32_t addr) {
    asm volatile("ldmatrix.sync.aligned.m8n8.x4.shared.b16 {%0,%1,%2,%3}, [%4];"
                 : "=r"(r[0]), "=r"(r[1]), "=r"(r[2]), "=r"(r[3]) : "r"(addr));
}
__device__ __forceinline__ void mma_s8(int c[4], const uint32_t a[4], const uint32_t b[2]) {
    asm volatile(
        "mma.sync.aligned.m16n8k32.row.col.s32.s8.s8.s32 "
        "{%0,%1,%2,%3}, {%4,%5,%6,%7}, {%8,%9}, {%0,%1,%2,%3};"
        : "+r"(c[0]), "+r"(c[1]), "+r"(c[2]), "+r"(c[3])
        : "r"(a[0]), "r"(a[1]), "r"(a[2]), "r"(a[3]), "r"(b[0]), "r"(b[1]));
}

// ---------------------------------------------------------------------------
// Kernel 1: L2-normalize -> int8 (x256). One warp per row, full retention,
// zero block barriers (measured-best variant: 12.9-13.2us).
// ---------------------------------------------------------------------------
__global__ void k_normalize(const float* __restrict__ e0,
                            const float* __restrict__ e1,
                            const float* __restrict__ e2) {
    const int lane = threadIdx.x & 31;
    const int row  = blockIdx.x * 8 + (threadIdx.x >> 5);
    if (lane == 0) { g_denom[row] = 0.f; g_num[row] = 0.f; }

    const float* src;
    if (row < BROWS)            src = e0 + (size_t)row * D;
    else if (row < 2 * BROWS)   src = e1 + (size_t)(row - BROWS) * D;
    else                        src = e2 + (size_t)(row - 2 * BROWS) * D;
    const float4* s4 = (const float4*)src;

    float4 v[16];
    float ss = 0.f;
    #pragma unroll
    for (int it = 0; it < 16; it++) {
        v[it] = s4[lane + 32 * it];
        ss += v[it].x * v[it].x + v[it].y * v[it].y
            + v[it].z * v[it].z + v[it].w * v[it].w;
    }

    #pragma unroll
    for (int o = 16; o; o >>= 1) ss += __shfl_xor_sync(0xffffffffu, ss, o);

    float inv = 256.0f / fmaxf(sqrtf(ss), 1e-12f);

    uint32_t* d32 = (uint32_t*)(g_z8 + (size_t)row * D);
    #pragma unroll
    for (int it = 0; it < 16; it++) {
        d32[lane + 32 * it] =
            pack4_s8(v[it].x * inv, v[it].y * inv, v[it].z * inv, v[it].w * inv);
    }
}

// ---------------------------------------------------------------------------
// Kernel 2: upper-triangle tiles, int8 mma, 3-stage cp.async pipeline,
// swizzled smem, one barrier per chunk. Chunk loop FULLY unrolled so buffer
// indices / smem bases / staging predicate are compile-time constants.
// 256 threads = 8 warps, 2(M) x 4(N).
// ---------------------------------------------------------------------------
__device__ __forceinline__ void stage_chunk(uint32_t sb, uint32_t aOff, uint32_t bOff,
                                            int rowBase, int colBase, int k0, int tid) {
    #pragma unroll
    for (int it = 0; it < 4; it++) {
        int id = tid + it * 256;          // 0..1023
        int r  = id >> 3;                 // 0..127
        int cc = id & 7;                  // 16B chunk within row
        uint32_t o = (uint32_t)(r * 128 + ((cc ^ (r & 7)) << 4));
        cp16(sb + aOff + o, g_z8 + (size_t)(rowBase + r) * D + k0 + cc * 16);
        cp16(sb + bOff + o, g_z8 + (size_t)(colBase + r) * D + k0 + cc * 16);
    }
}

__global__ __launch_bounds__(256, 2)
void k_sim() {
    extern __shared__ char smem[];
    const uint32_t sb = smem_u32(smem);
    float* rs = (float*)(smem + OFF_RS);
    float* cs = (float*)(smem + OFF_CS);

    // Triangular decode: t = i*(i+1)/2 + j with j <= i; rowTile=j, colTile=i
    int t = blockIdx.x;
    int i = (int)((sqrtf(8.0f * (float)t + 1.0f) - 1.0f) * 0.5f);
    while ((i + 1) * (i + 2) / 2 <= t) i++;
    while (i * (i + 1) / 2 > t) i--;
    int j = t - i * (i + 1) / 2;

    const int rowBase = j * TILE;
    const int colBase = i * TILE;
    const bool diagTile = (i == j);

    const int tid  = threadIdx.x;
    const int wid  = tid >> 5;
    const int lane = tid & 31;
    const int mBase = (wid >> 2) * 64;   // warpM in {0,1}
    const int nBase = (wid & 3) * 32;    // warpN in {0..3}
    const int gid = lane >> 2;
    const int tig = lane & 3;

    if (tid < 2 * TILE) ((float*)(smem + OFF_RS))[tid] = 0.f;

    // ldmatrix lane addressing (swizzled)
    const int aRow = mBase + (lane & 15);          // +ms*16 preserves &7
    const uint32_t aXor = (uint32_t)(aRow & 7);
    const uint32_t aHi  = (lane & 16) ? 1u : 0u;
    const int bRow = nBase + ((lane & 16) ? 8 : 0) + (lane & 7);   // +p*16 preserves &7
    const uint32_t bXor = (uint32_t)(bRow & 7);
    const uint32_t bHi  = (lane & 8) ? 1u : 0u;

    int acc[4][4][4] = {};               // [msub][nsub][frag], int32

    // prologue: prefetch chunks 0,1
    stage_chunk(sb, OFF_A(0), OFF_B(0), rowBase, colBase, 0, tid);
    CP_COMMIT();
    stage_chunk(sb, OFF_A(1), OFF_B(1), rowBase, colBase, KCB, tid);
    CP_COMMIT();

    #pragma unroll
    for (int c = 0; c < NCHUNK; c++) {
        const int buf = c % 3;           // compile-time after full unroll
        if (c == NCHUNK - 1) { CP_WAIT0(); } else { CP_WAIT1(); }
        __syncthreads();

        const uint32_t aB = sb + OFF_A(buf);
        const uint32_t bB = sb + OFF_B(buf);

        // 4 k-steps of 32 int8 (32 bytes = 2 swizzled chunks) each
        #pragma unroll
        for (int kk = 0; kk < KCB; kk += 32) {
            const uint32_t ch = (uint32_t)(kk >> 4);
            uint32_t a[4][4];
            uint32_t b[2][4];            // [n-pair][(ns even:0,1)(ns odd:2,3)]
            #pragma unroll
            for (int ms = 0; ms < 4; ms++)
                ldsm4(a[ms], aB + (uint32_t)(aRow + ms * 16) * 128
                                + (((ch + aHi) ^ aXor) << 4));
            #pragma unroll
            for (int p = 0; p < 2; p++)
                ldsm4(b[p], bB + (uint32_t)(bRow + p * 16) * 128
                               + (((ch + bHi) ^ bXor) << 4));

            #pragma unroll
            for (int ms = 0; ms < 4; ms++) {
                mma_s8(acc[ms][0], a[ms], &b[0][0]);
                mma_s8(acc[ms][1], a[ms], &b[0][2]);
                mma_s8(acc[ms][2], a[ms], &b[1][0]);
                mma_s8(acc[ms][3], a[ms], &b[1][2]);
            }
        }

        // stage chunk c+2 into buffer (c+2)%3 (its last reader finished at
        // iter c-1, proven by this iteration's barrier)
        if (c + 2 < NCHUNK) {
            const int nb = (c + 2) % 3;  // compile-time after full unroll
            stage_chunk(sb, OFF_A(nb), OFF_B(nb), rowBase, colBase, (c + 2) * KCB, tid);
            CP_COMMIT();
        }
    }

    // exp, diagonal exclusion, row + column sums
    // acc = 65536 * sim  ->  scale = 10*log2(e)/65536
    const float SCALE = 14.4269504088896340736f / 65536.0f;

    float colAcc[4][2] = {};

    #pragma unroll
    for (int ms = 0; ms < 4; ms++) {
        int r0 = mBase + ms * 16 + gid;
        float s0 = 0.f, s1 = 0.f;
        #pragma unroll
        for (int ns = 0; ns < 4; ns++) {
            int c0 = nBase + ns * 8 + tig * 2;
            float v0 = fast_ex2((float)acc[ms][ns][0] * SCALE);
            float v1 = fast_ex2((float)acc[ms][ns][1] * SCALE);
            float v2 = fast_ex2((float)acc[ms][ns][2] * SCALE);
            float v3 = fast_ex2((float)acc[ms][ns][3] * SCALE);
            if (diagTile) {
                if (r0 == c0)         v0 = 0.f;
                if (r0 == c0 + 1)     v1 = 0.f;
                if (r0 + 8 == c0)     v2 = 0.f;
                if (r0 + 8 == c0 + 1) v3 = 0.f;
            }
            s0 += v0 + v1;
            s1 += v2 + v3;
            colAcc[ns][0] += v0 + v2;
            colAcc[ns][1] += v1 + v3;
        }
        s0 += __shfl_xor_sync(0xffffffffu, s0, 1);
        s0 += __shfl_xor_sync(0xffffffffu, s0, 2);
        s1 += __shfl_xor_sync(0xffffffffu, s1, 1);
        s1 += __shfl_xor_sync(0xffffffffu, s1, 2);
        if (tig == 0) {
            atomicAdd(&rs[r0], s0);
            atomicAdd(&rs[r0 + 8], s1);
        }
    }

    if (!diagTile) {
        #pragma unroll
        for (int ns = 0; ns < 4; ns++) {
            float c0v = colAcc[ns][0];
            float c1v = colAcc[ns][1];
            #pragma unroll
            for (int o = 4; o <= 16; o <<= 1) {
                c0v += __shfl_xor_sync(0xffffffffu, c0v, o);
                c1v += __shfl_xor_sync(0xffffffffu, c1v, o);
            }
            if (gid == 0) {
                int c0 = nBase + ns * 8 + tig * 2;
                atomicAdd(&cs[c0], c0v);
                atomicAdd(&cs[c0 + 1], c1v);
            }
        }
    }
    __syncthreads();

    if (tid < TILE) {
        bool inNum = ((rowBase < BIJ) == (colBase < BIJ));
        float rv = rs[tid];
        atomicAdd(&g_denom[rowBase + tid], rv);
        if (inNum) atomicAdd(&g_num[rowBase + tid], rv);
        if (!diagTile) {
            float cv = cs[tid];
            atomicAdd(&g_denom[colBase + tid], cv);
            if (inNum) atomicAdd(&g_num[colBase + tid], cv);
        }
    }
}

// ---------------------------------------------------------------------------
// Kernel 3: per-row loss and final scalar. log via MUFU lg2.
// ---------------------------------------------------------------------------
__global__ void k_loss(float* __restrict__ out) {
    const float LN2 = 0.6931471805599453f;
    int tid = threadIdx.x;
    float s = 0.f;
    for (int ii = tid; ii < SIZE; ii += 512) {
        float cntm1 = (ii < BIJ) ? (float)(BIJ - 1) : (float)(BROWS - 1);
        s += (fast_lg2(g_denom[ii]) - fast_lg2(g_num[ii]) + fast_lg2(cntm1)) * LN2;
    }
    #pragma unroll
    for (int o = 16; o; o >>= 1) s += __shfl_xor_sync(0xffffffffu, s, o);
    __shared__ float ws[16];
    if ((tid & 31) == 0) ws[tid >> 5] = s;
    __syncthreads();
    if (tid == 0) {
        float tsum = 0.f;
        #pragma unroll
        for (int w = 0; w < 16; w++) tsum += ws[w];
        out[0] = tsum / (float)SIZE;
    }
}

// ---------------------------------------------------------------------------
extern "C" void kernel_launch(void* const* d_in, const int* in_sizes, int n_in,
                              void* d_out, int out_size) {
    const float* emb_i = (const float*)d_in[0];
    const float* emb_j = (const float*)d_in[1];
    const float* emb_k = (const float*)d_in[2];
    float* out = (float*)d_out;

    cudaFuncSetAttribute(k_sim, cudaFuncAttributeMaxDynamicSharedMemorySize, SMEM_TOTAL);

    k_normalize<<<SIZE / 8, 256>>>(emb_i, emb_j, emb_k);
    k_sim<<<NBLOCKS, 256, SMEM_TOTAL>>>();
    k_loss<<<1, 512>>>(out);
}